// round 1
// baseline (speedup 1.0000x reference)
#include <cuda_runtime.h>
#include <math.h>

// Problem constants (fixed by reference)
constexpr int B = 8, C = 96, G = 64 /*PY*PX*/, J = 17, K = 96;
constexpr float WIDTH = 128.0f;

constexpr int KPT = 6;          // keypoints per thread
constexpr int KG  = K / KPT;    // 16 k-groups
constexpr int NT  = KG * J;     // 272 threads: tid = kg*17 + j

__global__ __launch_bounds__(NT, 4)
void oks_assign_kernel(const float* __restrict__ pose_pool,   // [B,C,8,8,J,2]
                       const float* __restrict__ keypoints,   // [B,K,J,3]
                       const float* __restrict__ areas,       // [B,K]
                       const float* __restrict__ transforms,  // [B,3,3]
                       const float* __restrict__ tinv,        // [B,3,3]
                       const int*   __restrict__ hflip,       // [B]
                       const float* __restrict__ sigmas,      // [J]
                       float* __restrict__ out)
{
    __shared__ float2 pose_sh[G * J];        // 8704 B: poses in image coords
    __shared__ float  vis_sum_sh[K];
    __shared__ float  best_sh[K * 18];       // [k][j] padded; reused as parts[G*J]
    __shared__ float  person_sh[K];
    __shared__ int    ks_sh;

    const int bc  = blockIdx.x;
    const int b   = bc / C;
    const int tid = threadIdx.x;

    // ---- Setup: inverse-affine + hflip transform of pose pool into SMEM ----
    const float* Ti = tinv + b * 9;
    const float ti00 = Ti[0], ti01 = Ti[1], ti02 = Ti[2];
    const float ti10 = Ti[3], ti11 = Ti[4], ti12 = Ti[5];
    const bool flip = hflip[b] > 0;

    const float2* pp = reinterpret_cast<const float2*>(pose_pool) + (size_t)bc * (G * J);
    for (int idx = tid; idx < G * J; idx += NT) {
        float2 p = pp[idx];
        float px = flip ? (WIDTH - 1.0f - p.x) : p.x;
        float py = p.y;
        pose_sh[idx] = make_float2(px * ti00 + py * ti01 + ti02,
                                   px * ti10 + py * ti11 + ti12);
    }

    const float* kb = keypoints + (size_t)b * K * J * 3;
    if (tid < K) {
        const float* kp = kb + (size_t)tid * J * 3;
        float s = 0.0f;
        #pragma unroll
        for (int j = 0; j < J; j++) s += (kp[j * 3 + 2] > 0.0f) ? 1.0f : 0.0f;
        vis_sum_sh[tid] = fmaxf(s, 1.0f);
    }
    __syncthreads();

    // ---- Pass A: min_g d^2 for (my j, my 6 k's) over the 64-pose grid ----
    const int j  = tid % J;
    const int kg = tid / J;
    const int k0 = kg * KPT;

    float kx[KPT], ky[KPT], mind[KPT];
    #pragma unroll
    for (int i = 0; i < KPT; i++) {
        const float* kp = kb + (size_t)(k0 + i) * J * 3 + j * 3;
        kx[i] = kp[0];
        ky[i] = kp[1];
        mind[i] = 3.402823466e+38f;
    }

    #pragma unroll 8
    for (int g = 0; g < G; g++) {
        float2 p = pose_sh[g * J + j];
        #pragma unroll
        for (int i = 0; i < KPT; i++) {
            float dx = p.x - kx[i];
            float dy = p.y - ky[i];
            float d  = fmaf(dx, dx, dy * dy);
            mind[i]  = fminf(mind[i], d);
        }
    }

    // best[k][j] = vis * exp(-min_d / denom)
    float sj   = sigmas[j] * 2.0f;
    float varj = sj * sj;
    #pragma unroll
    for (int i = 0; i < KPT; i++) {
        int k = k0 + i;
        float v     = (kb[(size_t)k * J * 3 + j * 3 + 2] > 0.0f) ? 1.0f : 0.0f;
        float denom = fmaxf(2.0f * varj * areas[b * K + k], 1e-6f);
        best_sh[k * 18 + j] = v * expf(-mind[i] / denom);
    }
    __syncthreads();

    // person_best[k] = sum_j best / vis_sum
    if (tid < K) {
        float s = 0.0f;
        #pragma unroll
        for (int jj = 0; jj < J; jj++) s += best_sh[tid * 18 + jj];
        person_sh[tid] = s / vis_sum_sh[tid];
    }
    __syncthreads();

    // argmax over K (first max wins, matching jnp.argmax)
    if (tid == 0) {
        float bv = person_sh[0]; int bi = 0;
        for (int k = 1; k < K; k++) {
            float v = person_sh[k];
            if (v > bv) { bv = v; bi = k; }
        }
        ks_sh = bi;
    }
    __syncthreads();
    const int ks = ks_sh;

    // ---- Pass B: outputs for the assigned GT ks ----
    const float  area_s = areas[b * K + ks];
    const float* kpsel  = kb + (size_t)ks * J * 3;
    float* parts = best_sh;  // reuse (all best_sh readers synced above)

    float* out_parts  = out;
    float* out_person = out + (size_t)B * C * G * J;
    float* out_posegt = out_person + (size_t)B * C * G;

    for (int idx = tid; idx < G * J; idx += NT) {
        int jj = idx % J;
        float kxx = kpsel[jj * 3 + 0];
        float kyy = kpsel[jj * 3 + 1];
        float v   = (kpsel[jj * 3 + 2] > 0.0f) ? 1.0f : 0.0f;
        float s2  = sigmas[jj] * 2.0f;
        float denom = fmaxf(2.0f * s2 * s2 * area_s, 1e-6f);
        float2 p = pose_sh[idx];
        float dx = p.x - kxx, dy = p.y - kyy;
        float oks = v * expf(-fmaf(dx, dx, dy * dy) / denom);
        parts[idx] = oks;
        out_parts[(size_t)bc * (G * J) + idx] = oks;
    }
    __syncthreads();

    if (tid < G) {
        float s = 0.0f;
        #pragma unroll
        for (int jj = 0; jj < J; jj++) s += parts[tid * J + jj];
        out_person[(size_t)bc * G + tid] = s / vis_sum_sh[ks];
    }

    if (tid < J) {
        const float* t = transforms + b * 9;
        float kxx = kpsel[tid * 3 + 0];
        float kyy = kpsel[tid * 3 + 1];
        float kvv = kpsel[tid * 3 + 2];
        float gx = t[0] * kxx + t[1] * kyy + t[2];
        float gy = t[3] * kxx + t[4] * kyy + t[5];
        if (flip) gx = WIDTH - 1.0f - gx;
        float s2 = sigmas[tid] * 2.0f;
        float gv = (t[0] * t[4]) * (area_s * s2 * s2) * ((kvv > 0.0f) ? 1.0f : 0.0f);
        float* og = out_posegt + ((size_t)bc * J + tid) * 3;
        og[0] = gx; og[1] = gy; og[2] = gv;
    }
}

extern "C" void kernel_launch(void* const* d_in, const int* in_sizes, int n_in,
                              void* d_out, int out_size)
{
    const float* pose_pool  = (const float*)d_in[0];
    const float* keypoints  = (const float*)d_in[1];
    const float* areas      = (const float*)d_in[2];
    const float* transforms = (const float*)d_in[3];
    const float* tinv       = (const float*)d_in[4];
    const int*   hflip      = (const int*)  d_in[5];
    const float* sigmas     = (const float*)d_in[6];
    float* out = (float*)d_out;

    oks_assign_kernel<<<B * C, NT>>>(pose_pool, keypoints, areas, transforms,
                                     tinv, hflip, sigmas, out);
}